// round 7
// baseline (speedup 1.0000x reference)
#include <cuda_runtime.h>
#include <cstdint>
#include <cfloat>

#define NROWS   16000
#define NBANDS  64
#define HIDDEN  512
#define LATENT  256
#define GRP     8
#define GD      32
#define KCB     1024

// ---------------- scratch (allocation-free) ----------------
__device__ float g_hb[NROWS * HIDDEN];      // hidden, tf32-big
__device__ float g_hr[NROWS * HIDDEN];      // hidden, tf32-res
__device__ float g_zeb[NROWS * LATENT];
__device__ float g_zer[NROWS * LATENT];
__device__ float g_zqb[NROWS * LATENT];
__device__ float g_zqr[NROWS * LATENT];
__device__ float g_bab[NROWS * NBANDS];     // bands split
__device__ float g_bar[NROWS * NBANDS];
#define WT_TOTAL 327680
__device__ float g_wtb[WT_TOTAL];
__device__ float g_wtr[WT_TOTAL];
__device__ float g_cbb[GRP * KCB * GD];
__device__ float g_cbr[GRP * KCB * GD];
__device__ float g_cn2[GRP * KCB];
__device__ float g_loss_part[1024];
__device__ unsigned int g_cnt = 0;

// ---------------- helpers ----------------
__device__ __forceinline__ uint32_t smem_u32(const void* p) {
    uint32_t a;
    asm("{ .reg .u64 t; cvta.to.shared.u64 t, %1; cvt.u32.u64 %0, t; }" : "=r"(a) : "l"(p));
    return a;
}
__device__ __forceinline__ uint32_t tf32_of(float x) {
    uint32_t r;
    asm("cvt.rna.tf32.f32 %0, %1;" : "=r"(r) : "f"(x));
    return r;
}
__device__ __forceinline__ void cp_async16(uint32_t saddr, const void* g) {
    asm volatile("cp.async.cg.shared.global [%0], [%1], 16;" :: "r"(saddr), "l"(g));
}
#define CP_COMMIT() asm volatile("cp.async.commit_group;" ::: "memory")
#define CP_WAIT0()  asm volatile("cp.async.wait_group 0;" ::: "memory")
#define CP_WAIT1()  asm volatile("cp.async.wait_group 1;" ::: "memory")

__device__ __forceinline__ void mma_tf32(float* c, const uint32_t* a, uint32_t b0, uint32_t b1) {
    asm volatile(
        "mma.sync.aligned.m16n8k8.row.col.f32.tf32.tf32.f32 "
        "{%0,%1,%2,%3}, {%4,%5,%6,%7}, {%8,%9}, {%0,%1,%2,%3};"
        : "+f"(c[0]), "+f"(c[1]), "+f"(c[2]), "+f"(c[3])
        : "r"(a[0]), "r"(a[1]), "r"(a[2]), "r"(a[3]), "r"(b0), "r"(b1));
}

// ---------------- fused split kernels ----------------
__global__ void split_all(const float* __restrict__ ew1, const float* __restrict__ ew2,
                          const float* __restrict__ dw1, const float* __restrict__ dw2,
                          const float* __restrict__ bands,
                          float* __restrict__ wtb, float* __restrict__ wtr,
                          float* __restrict__ bab, float* __restrict__ bar)
{
    int i = blockIdx.x * 256 + threadIdx.x;
    const float* src; float *db, *dr; int off;
    if      (i < 32768)   { src = ew1;   db = wtb;          dr = wtr;          off = i; }
    else if (i < 163840)  { src = ew2;   db = wtb + 32768;  dr = wtr + 32768;  off = i - 32768; }
    else if (i < 294912)  { src = dw1;   db = wtb + 163840; dr = wtr + 163840; off = i - 163840; }
    else if (i < 327680)  { src = dw2;   db = wtb + 294912; dr = wtr + 294912; off = i - 294912; }
    else if (i < 1351680) { src = bands; db = bab;          dr = bar;          off = i - 327680; }
    else return;
    float x = src[off];
    uint32_t b = tf32_of(x);
    db[off] = __uint_as_float(b);
    dr[off] = __uint_as_float(tf32_of(x - __uint_as_float(b)));
}

__global__ void csplit(const float* __restrict__ cb, float* __restrict__ cbb,
                       float* __restrict__ cbr, float* __restrict__ cn2)
{
    int row = blockIdx.x * 256 + threadIdx.x;
    if (row >= GRP * KCB) return;
    const float* src = cb + (size_t)row * GD;
    float s = 0.0f;
    #pragma unroll
    for (int d = 0; d < GD; d++) {
        float x = src[d];
        uint32_t b = tf32_of(x);
        cbb[(size_t)row * GD + d] = __uint_as_float(b);
        cbr[(size_t)row * GD + d] = __uint_as_float(tf32_of(x - __uint_as_float(b)));
        s = fmaf(x, x, s);
    }
    cn2[row] = s;
}

// ===========================================================================
// Tensor GEMM, fully pre-split operands (pure LDS+HMMA mainloop).
// C = act(A @ W + bias).  BM=128, BK=32, 512 threads = 16 warps (4M x 4N).
// Outputs: fp32 C (if OUT_F32) and/or tf32-split Cb/Cr (if OUT_SPLIT).
// ===========================================================================
template<int BN, bool RELU, bool OUT_F32, bool OUT_SPLIT>
__global__ __launch_bounds__(512, 1) void tgemm(
    const float* __restrict__ Ab, const float* __restrict__ Ar,
    const float* __restrict__ Wb, const float* __restrict__ Wr,
    const float* __restrict__ bias,
    float* __restrict__ C, float* __restrict__ Cb, float* __restrict__ Cr,
    int M, int N, int K)
{
    constexpr int BM = 128, BK = 32;
    constexpr int ASTR = 36, BSTR = BN + 8;
    constexpr int WN = BN / 4, NT = WN / 8;
    constexpr int ASZ = BM * ASTR;      // 4608
    constexpr int BSZ = BK * BSTR;

    extern __shared__ float sm[];
    float* AbS[2] = { sm,           sm + ASZ };
    float* ArS[2] = { sm + 2 * ASZ, sm + 3 * ASZ };
    float* BbS[2] = { sm + 4 * ASZ,           sm + 4 * ASZ + BSZ };
    float* BrS[2] = { sm + 4 * ASZ + 2 * BSZ, sm + 4 * ASZ + 3 * BSZ };

    const int tid  = threadIdx.x;
    const int wid  = tid >> 5;
    const int lane = tid & 31;
    const int grp  = lane >> 2;
    const int ctg  = lane & 3;
    const int wy   = wid & 3;
    const int wx   = wid >> 2;          // 0..3
    const int m0   = blockIdx.y * BM;
    const int n0   = blockIdx.x * BN;

    float acc[2][NT][4];
    #pragma unroll
    for (int mt = 0; mt < 2; mt++)
        #pragma unroll
        for (int nt = 0; nt < NT; nt++)
            #pragma unroll
            for (int q = 0; q < 4; q++) acc[mt][nt][q] = 0.0f;

    auto copy_chunk = [&](int ch, int buf) {
        const int k0 = ch * BK;
        uint32_t ab = smem_u32(AbS[buf]), ar = smem_u32(ArS[buf]);
        uint32_t bb = smem_u32(BbS[buf]), br = smem_u32(BrS[buf]);
        #pragma unroll
        for (int u = 0; u < 2; u++) {            // 1024 A slots / 512 thr
            int f = tid + u * 512;
            int r = f >> 3, q = f & 7;
            size_t gi = (size_t)(m0 + r) * K + k0 + q * 4;
            uint32_t so = (uint32_t)(r * ASTR + q * 4) * 4;
            cp_async16(ab + so, &Ab[gi]);
            cp_async16(ar + so, &Ar[gi]);
        }
        constexpr int BQ = BK * (BN / 4) / 512;  // 2 (BN=128) / 1 (BN=64)
        #pragma unroll
        for (int u = 0; u < BQ; u++) {
            int f = tid + u * 512;
            int kr = f / (BN / 4), nq = f % (BN / 4);
            size_t gi = (size_t)(k0 + kr) * N + n0 + nq * 4;
            uint32_t so = (uint32_t)(kr * BSTR + nq * 4) * 4;
            cp_async16(bb + so, &Wb[gi]);
            cp_async16(br + so, &Wr[gi]);
        }
        CP_COMMIT();
    };

    auto compute = [&](int buf) {
        const float* AbP = AbS[buf];
        const float* ArP = ArS[buf];
        const float* BbP = BbS[buf];
        const float* BrP = BrS[buf];
        #pragma unroll
        for (int ks = 0; ks < 4; ks++) {
            const int k8 = ks * 8;
            uint32_t fab[2][4], far[2][4];
            #pragma unroll
            for (int mt = 0; mt < 2; mt++) {
                const int rb = wy * 32 + mt * 16;
                fab[mt][0] = __float_as_uint(AbP[(rb + grp) * ASTR + k8 + ctg]);
                fab[mt][1] = __float_as_uint(AbP[(rb + 8 + grp) * ASTR + k8 + ctg]);
                fab[mt][2] = __float_as_uint(AbP[(rb + grp) * ASTR + k8 + 4 + ctg]);
                fab[mt][3] = __float_as_uint(AbP[(rb + 8 + grp) * ASTR + k8 + 4 + ctg]);
                far[mt][0] = __float_as_uint(ArP[(rb + grp) * ASTR + k8 + ctg]);
                far[mt][1] = __float_as_uint(ArP[(rb + 8 + grp) * ASTR + k8 + ctg]);
                far[mt][2] = __float_as_uint(ArP[(rb + grp) * ASTR + k8 + 4 + ctg]);
                far[mt][3] = __float_as_uint(ArP[(rb + 8 + grp) * ASTR + k8 + 4 + ctg]);
            }
            #pragma unroll
            for (int nt = 0; nt < NT; nt++) {
                const int col = wx * WN + nt * 8 + grp;
                uint32_t bb0 = __float_as_uint(BbP[(k8 + ctg) * BSTR + col]);
                uint32_t bb1 = __float_as_uint(BbP[(k8 + 4 + ctg) * BSTR + col]);
                uint32_t br0 = __float_as_uint(BrP[(k8 + ctg) * BSTR + col]);
                uint32_t br1 = __float_as_uint(BrP[(k8 + 4 + ctg) * BSTR + col]);
                #pragma unroll
                for (int mt = 0; mt < 2; mt++) {
                    mma_tf32(acc[mt][nt], fab[mt], bb0, bb1);
                    mma_tf32(acc[mt][nt], fab[mt], br0, br1);
                    mma_tf32(acc[mt][nt], far[mt], bb0, bb1);
                }
            }
        }
    };

    const int nch = K / BK;
    copy_chunk(0, 0);
    for (int ch = 0; ch < nch; ch++) {
        const int cur = ch & 1;
        if (ch + 1 < nch) { copy_chunk(ch + 1, cur ^ 1); CP_WAIT1(); }
        else              { CP_WAIT0(); }
        __syncthreads();
        compute(cur);
        __syncthreads();
    }

    // Epilogue
    #pragma unroll
    for (int mt = 0; mt < 2; mt++) {
        const int r0 = m0 + wy * 32 + mt * 16 + grp;
        #pragma unroll
        for (int nt = 0; nt < NT; nt++) {
            const int col = n0 + wx * WN + nt * 8 + 2 * ctg;
            float b0 = bias[col], b1 = bias[col + 1];
            float v[4];
            v[0] = acc[mt][nt][0] + b0; v[1] = acc[mt][nt][1] + b1;
            v[2] = acc[mt][nt][2] + b0; v[3] = acc[mt][nt][3] + b1;
            if (RELU) {
                #pragma unroll
                for (int q = 0; q < 4; q++) v[q] = fmaxf(v[q], 0.0f);
            }
            size_t o0 = (size_t)r0 * N + col;
            size_t o1 = (size_t)(r0 + 8) * N + col;
            if (OUT_F32) {
                *(float2*)&C[o0] = make_float2(v[0], v[1]);
                *(float2*)&C[o1] = make_float2(v[2], v[3]);
            }
            if (OUT_SPLIT) {
                float bg[4], rs[4];
                #pragma unroll
                for (int q = 0; q < 4; q++) {
                    bg[q] = __uint_as_float(tf32_of(v[q]));
                    rs[q] = __uint_as_float(tf32_of(v[q] - bg[q]));
                }
                *(float2*)&Cb[o0] = make_float2(bg[0], bg[1]);
                *(float2*)&Cb[o1] = make_float2(bg[2], bg[3]);
                *(float2*)&Cr[o0] = make_float2(rs[0], rs[1]);
                *(float2*)&Cr[o1] = make_float2(rs[2], rs[3]);
            }
        }
    }
}

// ===========================================================================
// VQ kernel v3: fully pre-split operands in the MMA loop; exact fp32 loss.
// Block = (128 rows, group g), 256 threads, 8 warps (4M x 2N), NT=8.
// ===========================================================================
#define VQ_SMEM_FLOATS (2*4608 + 4*4608 + 256 + 128 + 128)   // 28160

__global__ __launch_bounds__(256, 2) void vq_kernel(
    const float* __restrict__ ze,        // fp32 (for exact loss)
    const float* __restrict__ zeb, const float* __restrict__ zer,
    const float* __restrict__ cb,        // fp32 codebook (gather)
    const float* __restrict__ cbb, const float* __restrict__ cbr,
    const float* __restrict__ cn2,
    float* __restrict__ zq,
    float* __restrict__ zqb, float* __restrict__ zqr,
    float* __restrict__ idxf,
    float* __restrict__ losspart,
    float* __restrict__ lossout)
{
    extern __shared__ __align__(16) float sm[];
    float* Zb = sm;                 // [128][36]
    float* Zr = sm + 4608;
    float* CbBs[2] = { sm + 9216,  sm + 13824 };
    float* CbRs[2] = { sm + 18432, sm + 23040 };
    float* CNs  = sm + 27648;       // [2][128]
    float* zn   = sm + 27904;
    float* lsum = sm + 28032;

    const int tid  = threadIdx.x;
    const int wid  = tid >> 5;
    const int lane = tid & 31;
    const int grp  = lane >> 2;
    const int ctg  = lane & 3;
    const int wy   = wid & 3;
    const int wx   = wid >> 2;
    const int g    = blockIdx.y;
    const int row0 = blockIdx.x * 128;

    const float* cgb  = cb  + (size_t)g * KCB * GD;
    const float* cbbg = cbb + (size_t)g * KCB * GD;
    const float* cbrg = cbr + (size_t)g * KCB * GD;
    const float* cng  = cn2 + g * KCB;

    auto copyC = [&](int ch, int buf) {
        uint32_t sb_ = smem_u32(CbBs[buf]);
        uint32_t sr_ = smem_u32(CbRs[buf]);
        #pragma unroll
        for (int u = 0; u < 4; u++) {
            int f = tid + u * 256;
            int r = f >> 3, q = f & 7;
            size_t go = (size_t)(ch * 128 + r) * GD + q * 4;
            uint32_t so = (uint32_t)(r * 36 + q * 4) * 4;
            cp_async16(sb_ + so, cbbg + go);
            cp_async16(sr_ + so, cbrg + go);
        }
        if (tid < 32)
            cp_async16(smem_u32(CNs + buf * 128) + tid * 16, cng + ch * 128 + tid * 4);
    };

    // Prologue: Z split tiles + chunk0 (group0), chunk1 (group1)
    {
        uint32_t zb = smem_u32(Zb), zr = smem_u32(Zr);
        const float* zbB = zeb + (size_t)row0 * LATENT + g * GD;
        const float* zbR = zer + (size_t)row0 * LATENT + g * GD;
        #pragma unroll
        for (int u = 0; u < 4; u++) {
            int f = tid + u * 256;
            int r = f >> 3, q = f & 7;
            uint32_t so = (uint32_t)(r * 36 + q * 4) * 4;
            size_t go = (size_t)r * LATENT + q * 4;
            cp_async16(zb + so, zbB + go);
            cp_async16(zr + so, zbR + go);
        }
        copyC(0, 0);
        CP_COMMIT();
        copyC(1, 1);
        CP_COMMIT();
    }
    CP_WAIT1();
    __syncthreads();

    if (tid < 128) {
        float s = 0.0f;
        #pragma unroll
        for (int d = 0; d < 32; d++) {
            float z = Zb[tid * 36 + d] + Zr[tid * 36 + d];
            s = fmaf(z, z, s);
        }
        zn[tid] = s;
    }
    __syncthreads();

    float znr[4];
    znr[0] = zn[wy * 32 + grp];
    znr[1] = zn[wy * 32 + 8 + grp];
    znr[2] = zn[wy * 32 + 16 + grp];
    znr[3] = zn[wy * 32 + 24 + grp];

    float best[4];
    int   bidx[4];
    #pragma unroll
    for (int i = 0; i < 4; i++) { best[i] = FLT_MAX; bidx[i] = 0; }

    int buf = 0;
    for (int ch = 0; ch < 8; ch++) {
        float acc[2][8][4];
        #pragma unroll
        for (int mt = 0; mt < 2; mt++)
            #pragma unroll
            for (int nt = 0; nt < 8; nt++)
                #pragma unroll
                for (int q = 0; q < 4; q++) acc[mt][nt][q] = 0.0f;

        const float* Bb_ = CbBs[buf];
        const float* Br_ = CbRs[buf];
        #pragma unroll
        for (int ks = 0; ks < 4; ks++) {
            const int k8 = ks * 8;
            uint32_t fab[2][4], far[2][4];
            #pragma unroll
            for (int mt = 0; mt < 2; mt++) {
                const int rb = wy * 32 + mt * 16;
                fab[mt][0] = __float_as_uint(Zb[(rb + grp) * 36 + k8 + ctg]);
                fab[mt][1] = __float_as_uint(Zb[(rb + 8 + grp) * 36 + k8 + ctg]);
                fab[mt][2] = __float_as_uint(Zb[(rb + grp) * 36 + k8 + 4 + ctg]);
                fab[mt][3] = __float_as_uint(Zb[(rb + 8 + grp) * 36 + k8 + 4 + ctg]);
                far[mt][0] = __float_as_uint(Zr[(rb + grp) * 36 + k8 + ctg]);
                far[mt][1] = __float_as_uint(Zr[(rb + 8 + grp) * 36 + k8 + ctg]);
                far[mt][2] = __float_as_uint(Zr[(rb + grp) * 36 + k8 + 4 + ctg]);
                far[mt][3] = __float_as_uint(Zr[(rb + 8 + grp) * 36 + k8 + 4 + ctg]);
            }
            #pragma unroll
            for (int nt = 0; nt < 8; nt++) {
                const int col = wx * 64 + nt * 8 + grp;
                uint32_t bb0 = __float_as_uint(Bb_[col * 0 + (k8 + ctg) * 0 + 0]); // placeholder removed below
                (void)bb0;
                uint32_t b0 = __float_as_uint(Bb_[col * 36 * 0 + 0]); (void)b0;
                uint32_t vb0 = __float_as_uint(Bb_[(k8 + ctg) * 136 * 0 + 0]); (void)vb0;
                // actual loads (codebook stored [cw][36] row-major):
                uint32_t cb0 = __float_as_uint(Bb_[col * 36 + k8 + ctg]);
                uint32_t cb1 = __float_as_uint(Bb_[col * 36 + k8 + 4 + ctg]);
                uint32_t cr0 = __float_as_uint(Br_[col * 36 + k8 + ctg]);
                uint32_t cr1 = __float_as_uint(Br_[col * 36 + k8 + 4 + ctg]);
                #pragma unroll
                for (int mt = 0; mt < 2; mt++) {
                    mma_tf32(acc[mt][nt], fab[mt], cb0, cb1);
                    mma_tf32(acc[mt][nt], fab[mt], cr0, cr1);
                    mma_tf32(acc[mt][nt], far[mt], cb0, cb1);
                }
            }
        }

        const float* CNc = CNs + buf * 128;
        #pragma unroll
        for (int nt = 0; nt < 8; nt++) {
            const int cbase = wx * 64 + nt * 8 + 2 * ctg;
            float cn0 = CNc[cbase], cn1 = CNc[cbase + 1];
            int   k0  = ch * 128 + cbase;
            #pragma unroll
            for (int mt = 0; mt < 2; mt++) {
                float d00 = znr[mt * 2 + 0] + fmaf(-2.0f, acc[mt][nt][0], cn0);
                float d01 = znr[mt * 2 + 0] + fmaf(-2.0f, acc[mt][nt][1], cn1);
                float d10 = znr[mt * 2 + 1] + fmaf(-2.0f, acc[mt][nt][2], cn0);
                float d11 = znr[mt * 2 + 1] + fmaf(-2.0f, acc[mt][nt][3], cn1);
                if (d00 < best[mt * 2])     { best[mt * 2] = d00;     bidx[mt * 2] = k0; }
                if (d01 < best[mt * 2])     { best[mt * 2] = d01;     bidx[mt * 2] = k0 + 1; }
                if (d10 < best[mt * 2 + 1]) { best[mt * 2 + 1] = d10; bidx[mt * 2 + 1] = k0; }
                if (d11 < best[mt * 2 + 1]) { best[mt * 2 + 1] = d11; bidx[mt * 2 + 1] = k0 + 1; }
            }
        }
        __syncthreads();
        if (ch + 2 < 8) { copyC(ch + 2, buf); CP_COMMIT(); }
        if (ch + 1 < 8) {
            if (ch + 2 < 8) CP_WAIT1(); else CP_WAIT0();
            __syncthreads();
        }
        buf ^= 1;
    }

    // Cross-thread argmin reduction (8 slots/row)
    float* redV = CbBs[0];
    int*   redI = (int*)(CbBs[0] + 1024);
    #pragma unroll
    for (int s = 0; s < 4; s++) {
        int row = wy * 32 + (s >> 1) * 16 + (s & 1) * 8 + grp;
        redV[row * 8 + wx * 4 + ctg] = best[s];
        redI[row * 8 + wx * 4 + ctg] = bidx[s];
    }
    __syncthreads();

    if (tid < 128) {
        int   r  = tid;
        float bv = redV[r * 8];
        int   bi = redI[r * 8];
        #pragma unroll
        for (int t = 1; t < 8; t++) {
            float v  = redV[r * 8 + t];
            int   i2 = redI[r * 8 + t];
            if (v < bv || (v == bv && i2 < bi)) { bv = v; bi = i2; }
        }
        int grow = row0 + r;
        idxf[(size_t)grow * GRP + g] = (float)bi;

        const float* zrow = ze + (size_t)grow * LATENT + g * GD;    // exact fp32
        const float* cw   = cgb  + (size_t)bi * GD;
        const float* cwb  = cbbg + (size_t)bi * GD;
        const float* cwr  = cbrg + (size_t)bi * GD;
        float* zqo  = zq  + (size_t)grow * LATENT + g * GD;
        float* zqbo = zqb + (size_t)grow * LATENT + g * GD;
        float* zqro = zqr + (size_t)grow * LATENT + g * GD;
        float diff2 = 0.0f;
        #pragma unroll
        for (int dq = 0; dq < 8; dq++) {
            float4 c4 = *(const float4*)&cw[dq * 4];
            float4 z4 = *(const float4*)&zrow[dq * 4];
            float d0 = c4.x - z4.x, d1 = c4.y - z4.y;
            float d2 = c4.z - z4.z, d3 = c4.w - z4.w;
            diff2 = fmaf(d0, d0, diff2);
            diff2 = fmaf(d1, d1, diff2);
            diff2 = fmaf(d2, d2, diff2);
            diff2 = fmaf(d3, d3, diff2);
            *(float4*)&zqo[dq * 4]  = c4;
            *(float4*)&zqbo[dq * 4] = *(const float4*)&cwb[dq * 4];
            *(float4*)&zqro[dq * 4] = *(const float4*)&cwr[dq * 4];
        }
        lsum[r] = diff2;
    }
    __syncthreads();

    __shared__ bool is_last;
    if (tid == 0) {
        float s = 0.0f;
        for (int r = 0; r < 128; r++) s += lsum[r];
        losspart[blockIdx.y * gridDim.x + blockIdx.x] = s;
        __threadfence();
        unsigned int t = atomicAdd(&g_cnt, 1u);
        is_last = (t == (unsigned int)(gridDim.x * gridDim.y - 1));
    }
    __syncthreads();

    if (is_last) {
        int npart = gridDim.x * gridDim.y;
        float v = 0.0f;
        for (int i = tid; i < npart; i += 256) v += losspart[i];
        redV[tid] = v;
        __syncthreads();
        for (int off = 128; off > 0; off >>= 1) {
            if (tid < off) redV[tid] += redV[tid + off];
            __syncthreads();
        }
        if (tid == 0) {
            lossout[0] = redV[0] * (1.0f / 1024000.0f);
            g_cnt = 0;
        }
    }
}

// ===========================================================================
extern "C" void kernel_launch(void* const* d_in, const int* in_sizes, int n_in,
                              void* d_out, int out_size)
{
    const float* bands = (const float*)d_in[0];
    const float* ew1   = (const float*)d_in[1];
    const float* eb1   = (const float*)d_in[2];
    const float* ew2   = (const float*)d_in[3];
    const float* eb2   = (const float*)d_in[4];
    const float* cb    = (const float*)d_in[5];
    const float* dw1   = (const float*)d_in[6];
    const float* db1   = (const float*)d_in[7];
    const float* dw2   = (const float*)d_in[8];
    const float* db2   = (const float*)d_in[9];

    float* out  = (float*)d_out;
    float* bhat = out;
    float* ze   = bhat + 1024000;
    float* zq   = ze   + 4096000;
    float* idxf = zq   + 4096000;
    float* loss = idxf + 128000;

    float *hb, *hr, *zeb, *zer, *zqb, *zqr, *bab, *bar, *wtb, *wtr, *cbb, *cbr, *cn2, *lpart;
    cudaGetSymbolAddress((void**)&hb,  g_hb);
    cudaGetSymbolAddress((void**)&hr,  g_hr);
    cudaGetSymbolAddress((void**)&zeb, g_zeb);
    cudaGetSymbolAddress((void**)&zer, g_zer);
    cudaGetSymbolAddress((void**)&zqb, g_zqb);
    cudaGetSymbolAddress((void**)&zqr, g_zqr);
    cudaGetSymbolAddress((void**)&bab, g_bab);
    cudaGetSymbolAddress((void**)&bar, g_bar);
    cudaGetSymbolAddress((void**)&wtb, g_wtb);
    cudaGetSymbolAddress((void**)&wtr, g_wtr);
    cudaGetSymbolAddress((void**)&cbb, g_cbb);
    cudaGetSymbolAddress((void**)&cbr, g_cbr);
    cudaGetSymbolAddress((void**)&cn2, g_cn2);
    cudaGetSymbolAddress((void**)&lpart, g_loss_part);

    float* e1b = wtb;          float* e1r = wtr;
    float* e2b = wtb + 32768;  float* e2r = wtr + 32768;
    float* d1b = wtb + 163840; float* d1r = wtr + 163840;
    float* d2b = wtb + 294912; float* d2r = wtr + 294912;

    const int SM128 = (4 * 4608 + 4 * 32 * 136) * 4;   // 143360
    const int SM64  = (4 * 4608 + 4 * 32 * 72) * 4;    // 110592
    cudaFuncSetAttribute((const void*)tgemm<128, true,  false, true >,
                         cudaFuncAttributeMaxDynamicSharedMemorySize, SM128);
    cudaFuncSetAttribute((const void*)tgemm<128, false, true,  true >,
                         cudaFuncAttributeMaxDynamicSharedMemorySize, SM128);
    cudaFuncSetAttribute((const void*)tgemm<64,  false, true,  false>,
                         cudaFuncAttributeMaxDynamicSharedMemorySize, SM64);
    cudaFuncSetAttribute((const void*)vq_kernel,
                         cudaFuncAttributeMaxDynamicSharedMemorySize, VQ_SMEM_FLOATS * 4);

    // Fused splits
    split_all<<<5280, 256>>>(ew1, ew2, dw1, dw2, bands, wtb, wtr, bab, bar);
    csplit<<<32, 256>>>(cb, cbb, cbr, cn2);

    // Encoder
    tgemm<128, true,  false, true ><<<dim3(HIDDEN / 128, NROWS / 128), 512, SM128>>>(
        bab, bar, e1b, e1r, eb1, nullptr, hb, hr, NROWS, HIDDEN, NBANDS);
    tgemm<128, false, true,  true ><<<dim3(LATENT / 128, NROWS / 128), 512, SM128>>>(
        hb, hr, e2b, e2r, eb2, ze, zeb, zer, NROWS, LATENT, HIDDEN);

    // VQ
    vq_kernel<<<dim3(NROWS / 128, GRP), 256, VQ_SMEM_FLOATS * 4>>>(
        ze, zeb, zer, cb, cbb, cbr, cn2, zq, zqb, zqr, idxf, lpart, loss);

    // Decoder
    tgemm<128, true,  false, true ><<<dim3(HIDDEN / 128, NROWS / 128), 512, SM128>>>(
        zqb, zqr, d1b, d1r, db1, nullptr, hb, hr, NROWS, HIDDEN, LATENT);
    tgemm<64,  false, true,  false><<<dim3(NBANDS / 64, NROWS / 128), 512, SM64>>>(
        hb, hr, d2b, d2r, db2, bhat, nullptr, nullptr, NROWS, NBANDS, HIDDEN);
}

// round 8
// speedup vs baseline: 1.2112x; 1.2112x over previous
#include <cuda_runtime.h>
#include <cstdint>
#include <cfloat>

#define NROWS   16000
#define NBANDS  64
#define HIDDEN  512
#define LATENT  256
#define GRP     8
#define GD      32
#define KCB     1024

__device__ float g_hidden[NROWS * HIDDEN];
__device__ float g_loss_part[1024];
__device__ unsigned int g_cnt = 0;

// Pre-split (tf32 big/res) weights, [K][N] layout, concatenated:
// e1 64x512 @0 | e2 512x256 @32768 | d1 256x512 @163840 | d2 512x64 @294912
#define WT_TOTAL 327680
__device__ float g_wtb[WT_TOTAL];
__device__ float g_wtr[WT_TOTAL];
// Pre-split codebook [G][K][32] + norms
__device__ float g_cbb[GRP * KCB * GD];
__device__ float g_cbr[GRP * KCB * GD];
__device__ float g_cn2[GRP * KCB];

// ===========================================================================
// Helpers
// ===========================================================================
__device__ __forceinline__ uint32_t smem_u32(const void* p) {
    uint32_t a;
    asm("{ .reg .u64 t; cvta.to.shared.u64 t, %1; cvt.u32.u64 %0, t; }" : "=r"(a) : "l"(p));
    return a;
}
__device__ __forceinline__ uint32_t tf32_of(float x) {
    uint32_t r;
    asm("cvt.rna.tf32.f32 %0, %1;" : "=r"(r) : "f"(x));
    return r;
}
__device__ __forceinline__ void cp_async16(uint32_t saddr, const void* g) {
    asm volatile("cp.async.cg.shared.global [%0], [%1], 16;" :: "r"(saddr), "l"(g));
}
#define CP_COMMIT() asm volatile("cp.async.commit_group;" ::: "memory")
#define CP_WAIT0()  asm volatile("cp.async.wait_group 0;" ::: "memory")
#define CP_WAIT1()  asm volatile("cp.async.wait_group 1;" ::: "memory")

__device__ __forceinline__ void mma_tf32(float* c, const uint32_t* a, uint32_t b0, uint32_t b1) {
    asm volatile(
        "mma.sync.aligned.m16n8k8.row.col.f32.tf32.tf32.f32 "
        "{%0,%1,%2,%3}, {%4,%5,%6,%7}, {%8,%9}, {%0,%1,%2,%3};"
        : "+f"(c[0]), "+f"(c[1]), "+f"(c[2]), "+f"(c[3])
        : "r"(a[0]), "r"(a[1]), "r"(a[2]), "r"(a[3]), "r"(b0), "r"(b1));
}

// ===========================================================================
// Fused split kernels (2 launches total)
// ===========================================================================
__global__ void split_all(const float* __restrict__ ew1, const float* __restrict__ ew2,
                          const float* __restrict__ dw1, const float* __restrict__ dw2,
                          float* __restrict__ wtb, float* __restrict__ wtr)
{
    int i = blockIdx.x * 256 + threadIdx.x;
    const float* src; int off;
    if      (i < 32768)  { src = ew1; off = i; }
    else if (i < 163840) { src = ew2; off = i - 32768; }
    else if (i < 294912) { src = dw1; off = i - 163840; }
    else if (i < 327680) { src = dw2; off = i - 294912; }
    else return;
    float x = src[off];
    uint32_t b = tf32_of(x);
    wtb[i] = __uint_as_float(b);
    wtr[i] = __uint_as_float(tf32_of(x - __uint_as_float(b)));
}

__global__ void csplit(const float* __restrict__ cb, float* __restrict__ cbb,
                       float* __restrict__ cbr, float* __restrict__ cn2)
{
    int row = blockIdx.x * 256 + threadIdx.x;
    if (row >= GRP * KCB) return;
    const float* src = cb + (size_t)row * GD;
    float s = 0.0f;
    #pragma unroll
    for (int d = 0; d < GD; d++) {
        float x = src[d];
        uint32_t b = tf32_of(x);
        cbb[(size_t)row * GD + d] = __uint_as_float(b);
        cbr[(size_t)row * GD + d] = __uint_as_float(tf32_of(x - __uint_as_float(b)));
        s = fmaf(x, x, s);
    }
    cn2[row] = s;
}

// ===========================================================================
// Tensor-core GEMM (3xtf32), B pre-split: C = act(A[M,K] @ W[K,N] + bias)
// BM in {64,128}, BK=32, 8 warps (4M x 2N), warp tile (BM/4) x (BN/2).
// A converted in-loop; 2-stage cp.async double buffering; 2 CTAs/SM.
// ===========================================================================
template<int BM, int BN, bool RELU>
__global__ __launch_bounds__(256, 2) void tgemm(
    const float* __restrict__ A,
    const float* __restrict__ Wb, const float* __restrict__ Wr,
    const float* __restrict__ bias, float* __restrict__ C,
    int M, int N, int K)
{
    constexpr int BK = 32;
    constexpr int ASTR = 36, BSTR = BN + 8;
    constexpr int WN = BN / 2, NT = WN / 8;
    constexpr int MT = BM / 64;                  // m16 tiles per warp
    constexpr int ASZ = BM * ASTR;
    constexpr int BSZ = BK * BSTR;
    constexpr int A_Q = BM / 32;                 // float4 per thread (A)
    constexpr int B_Q = BN / 32;                 // float4 per thread (B, per plane)

    extern __shared__ float sm[];
    float* AsBuf[2] = { sm, sm + ASZ };
    float* BbBuf[2] = { sm + 2 * ASZ, sm + 2 * ASZ + BSZ };
    float* BrBuf[2] = { sm + 2 * ASZ + 2 * BSZ, sm + 2 * ASZ + 3 * BSZ };

    const int tid = threadIdx.x;
    const int wid = tid >> 5;
    const int lane = tid & 31;
    const int grp = lane >> 2;
    const int ctg = lane & 3;
    const int wy  = wid & 3;
    const int wx  = wid >> 2;
    const int m0  = blockIdx.y * BM;
    const int n0  = blockIdx.x * BN;

    float acc[MT][NT][4];
    #pragma unroll
    for (int mt = 0; mt < MT; mt++)
        #pragma unroll
        for (int nt = 0; nt < NT; nt++)
            #pragma unroll
            for (int q = 0; q < 4; q++) acc[mt][nt][q] = 0.0f;

    auto copy_chunk = [&](int ch, int buf) {
        const int k0 = ch * BK;
        uint32_t as = smem_u32(AsBuf[buf]);
        uint32_t bb = smem_u32(BbBuf[buf]);
        uint32_t br = smem_u32(BrBuf[buf]);
        #pragma unroll
        for (int u = 0; u < A_Q; u++) {
            int f = tid + u * 256;
            int r = f >> 3, q = f & 7;
            cp_async16(as + (uint32_t)(r * ASTR + q * 4) * 4,
                       &A[(size_t)(m0 + r) * K + k0 + q * 4]);
        }
        #pragma unroll
        for (int u = 0; u < B_Q; u++) {
            int f = tid + u * 256;
            int kr = f / (BN / 4), nq = f % (BN / 4);
            size_t gi = (size_t)(k0 + kr) * N + n0 + nq * 4;
            uint32_t so = (uint32_t)(kr * BSTR + nq * 4) * 4;
            cp_async16(bb + so, &Wb[gi]);
            cp_async16(br + so, &Wr[gi]);
        }
        CP_COMMIT();
    };

    auto compute = [&](int buf) {
        const float* As = AsBuf[buf];
        const float* Bb = BbBuf[buf];
        const float* Br = BrBuf[buf];
        #pragma unroll
        for (int ks = 0; ks < 4; ks++) {
            const int k8 = ks * 8;
            uint32_t abig[MT][4], ares[MT][4];
            #pragma unroll
            for (int mt = 0; mt < MT; mt++) {
                const int rb = wy * (BM / 4) + mt * 16;
                float af[4];
                af[0] = As[(rb + grp) * ASTR + k8 + ctg];
                af[1] = As[(rb + 8 + grp) * ASTR + k8 + ctg];
                af[2] = As[(rb + grp) * ASTR + k8 + 4 + ctg];
                af[3] = As[(rb + 8 + grp) * ASTR + k8 + 4 + ctg];
                #pragma unroll
                for (int q = 0; q < 4; q++) {
                    abig[mt][q] = tf32_of(af[q]);
                    ares[mt][q] = tf32_of(af[q] - __uint_as_float(abig[mt][q]));
                }
            }
            #pragma unroll
            for (int nt = 0; nt < NT; nt++) {
                const int col = wx * WN + nt * 8 + grp;
                uint32_t bb0 = __float_as_uint(Bb[(k8 + ctg) * BSTR + col]);
                uint32_t bb1 = __float_as_uint(Bb[(k8 + 4 + ctg) * BSTR + col]);
                uint32_t br0 = __float_as_uint(Br[(k8 + ctg) * BSTR + col]);
                uint32_t br1 = __float_as_uint(Br[(k8 + 4 + ctg) * BSTR + col]);
                #pragma unroll
                for (int mt = 0; mt < MT; mt++) {
                    mma_tf32(acc[mt][nt], abig[mt], bb0, bb1);
                    mma_tf32(acc[mt][nt], abig[mt], br0, br1);
                    mma_tf32(acc[mt][nt], ares[mt], bb0, bb1);
                }
            }
        }
    };

    const int nch = K / BK;
    copy_chunk(0, 0);
    for (int ch = 0; ch < nch; ch++) {
        const int cur = ch & 1;
        if (ch + 1 < nch) { copy_chunk(ch + 1, cur ^ 1); CP_WAIT1(); }
        else              { CP_WAIT0(); }
        __syncthreads();
        compute(cur);
        __syncthreads();
    }

    #pragma unroll
    for (int mt = 0; mt < MT; mt++) {
        const int r0 = m0 + wy * (BM / 4) + mt * 16 + grp;
        #pragma unroll
        for (int nt = 0; nt < NT; nt++) {
            const int col = n0 + wx * WN + nt * 8 + 2 * ctg;
            float b0 = bias[col], b1 = bias[col + 1];
            float2 v0, v1;
            v0.x = acc[mt][nt][0] + b0; v0.y = acc[mt][nt][1] + b1;
            v1.x = acc[mt][nt][2] + b0; v1.y = acc[mt][nt][3] + b1;
            if (RELU) {
                v0.x = fmaxf(v0.x, 0.0f); v0.y = fmaxf(v0.y, 0.0f);
                v1.x = fmaxf(v1.x, 0.0f); v1.y = fmaxf(v1.y, 0.0f);
            }
            *(float2*)&C[(size_t)r0 * N + col] = v0;
            *(float2*)&C[(size_t)(r0 + 8) * N + col] = v1;
        }
    }
}

// ===========================================================================
// VQ kernel (round-6, known good): tensor-core cross term (3xtf32),
// pre-split codebook, double-buffered chunks, fused deterministic loss.
// ===========================================================================
#define VQ_SMEM_FLOATS (4608 + 9216 + 9216 + 256 + 128 + 128)

__global__ __launch_bounds__(256, 2) void vq_kernel(
    const float* __restrict__ ze,
    const float* __restrict__ cb,
    const float* __restrict__ cbb,
    const float* __restrict__ cbr,
    const float* __restrict__ cn2,
    float* __restrict__ zq,
    float* __restrict__ idxf,
    float* __restrict__ losspart,
    float* __restrict__ lossout)
{
    extern __shared__ __align__(16) float sm[];
    float* Zs = sm;                                        // [128][36]
    float* CbB[2] = { sm + 4608, sm + 4608 + 4608 };
    float* CbR[2] = { sm + 13824, sm + 13824 + 4608 };
    float* CNs  = sm + 23040;                              // [2][128]
    float* zn   = sm + 23296;
    float* lsum = sm + 23424;

    const int tid = threadIdx.x;
    const int wid = tid >> 5;
    const int lane = tid & 31;
    const int grp = lane >> 2;
    const int ctg = lane & 3;
    const int wy  = wid & 3;
    const int wx  = wid >> 2;
    const int g    = blockIdx.y;
    const int row0 = blockIdx.x * 128;

    const float* zbase = ze  + (size_t)row0 * LATENT + g * GD;
    const float* cgb   = cb  + (size_t)g * KCB * GD;
    const float* cbbg  = cbb + (size_t)g * KCB * GD;
    const float* cbrg  = cbr + (size_t)g * KCB * GD;
    const float* cng   = cn2 + g * KCB;

    auto copyC = [&](int ch, int buf) {
        uint32_t sb_ = smem_u32(CbB[buf]);
        uint32_t sr_ = smem_u32(CbR[buf]);
        #pragma unroll
        for (int u = 0; u < 4; u++) {
            int f = tid + u * 256;
            int r = f >> 3, q = f & 7;
            size_t go = (size_t)(ch * 128 + r) * GD + q * 4;
            uint32_t so = (uint32_t)(r * 36 + q * 4) * 4;
            cp_async16(sb_ + so, cbbg + go);
            cp_async16(sr_ + so, cbrg + go);
        }
        if (tid < 32)
            cp_async16(smem_u32(CNs + buf * 128) + tid * 16, cng + ch * 128 + tid * 4);
    };

    {
        uint32_t zs = smem_u32(Zs);
        #pragma unroll
        for (int u = 0; u < 4; u++) {
            int f = tid + u * 256;
            int r = f >> 3, q = f & 7;
            cp_async16(zs + (uint32_t)(r * 36 + q * 4) * 4,
                       zbase + (size_t)r * LATENT + q * 4);
        }
        copyC(0, 0);
        CP_COMMIT();
        copyC(1, 1);
        CP_COMMIT();
    }
    CP_WAIT1();
    __syncthreads();

    if (tid < 128) {
        float s = 0.0f;
        #pragma unroll
        for (int d = 0; d < 32; d++) { float z = Zs[tid * 36 + d]; s = fmaf(z, z, s); }
        zn[tid] = s;
    }
    __syncthreads();

    float znr[4];
    znr[0] = zn[wy * 32 + grp];
    znr[1] = zn[wy * 32 + 8 + grp];
    znr[2] = zn[wy * 32 + 16 + grp];
    znr[3] = zn[wy * 32 + 24 + grp];

    float best[4];
    int   bidx[4];
    #pragma unroll
    for (int i = 0; i < 4; i++) { best[i] = FLT_MAX; bidx[i] = 0; }

    int buf = 0;
    for (int ch = 0; ch < 8; ch++) {
        float acc[2][8][4];
        #pragma unroll
        for (int mt = 0; mt < 2; mt++)
            #pragma unroll
            for (int nt = 0; nt < 8; nt++)
                #pragma unroll
                for (int q = 0; q < 4; q++) acc[mt][nt][q] = 0.0f;

        const float* Bb_ = CbB[buf];
        const float* Br_ = CbR[buf];
        #pragma unroll
        for (int ks = 0; ks < 4; ks++) {
            const int k8 = ks * 8;
            uint32_t abig[2][4], ares[2][4];
            #pragma unroll
            for (int mt = 0; mt < 2; mt++) {
                const int rb = wy * 32 + mt * 16;
                float af[4];
                af[0] = Zs[(rb + grp) * 36 + k8 + ctg];
                af[1] = Zs[(rb + 8 + grp) * 36 + k8 + ctg];
                af[2] = Zs[(rb + grp) * 36 + k8 + 4 + ctg];
                af[3] = Zs[(rb + 8 + grp) * 36 + k8 + 4 + ctg];
                #pragma unroll
                for (int q = 0; q < 4; q++) {
                    abig[mt][q] = tf32_of(af[q]);
                    ares[mt][q] = tf32_of(af[q] - __uint_as_float(abig[mt][q]));
                }
            }
            #pragma unroll
            for (int nt = 0; nt < 8; nt++) {
                const int col = wx * 64 + nt * 8 + grp;
                uint32_t cb0 = __float_as_uint(Bb_[col * 36 + k8 + ctg]);
                uint32_t cb1 = __float_as_uint(Bb_[col * 36 + k8 + 4 + ctg]);
                uint32_t cr0 = __float_as_uint(Br_[col * 36 + k8 + ctg]);
                uint32_t cr1 = __float_as_uint(Br_[col * 36 + k8 + 4 + ctg]);
                #pragma unroll
                for (int mt = 0; mt < 2; mt++) {
                    mma_tf32(acc[mt][nt], abig[mt], cb0, cb1);
                    mma_tf32(acc[mt][nt], abig[mt], cr0, cr1);
                    mma_tf32(acc[mt][nt], ares[mt], cb0, cb1);
                }
            }
        }

        const float* CNc = CNs + buf * 128;
        #pragma unroll
        for (int nt = 0; nt < 8; nt++) {
            const int cbase = wx * 64 + nt * 8 + 2 * ctg;
            float cn0 = CNc[cbase], cn1 = CNc[cbase + 1];
            int   k0  = ch * 128 + cbase;
            #pragma unroll
            for (int mt = 0; mt < 2; mt++) {
                float d00 = znr[mt * 2 + 0] + fmaf(-2.0f, acc[mt][nt][0], cn0);
                float d01 = znr[mt * 2 + 0] + fmaf(-2.0f, acc[mt][nt][1], cn1);
                float d10 = znr[mt * 2 + 1] + fmaf(-2.0f, acc[mt][nt][2], cn0);
                float d11 = znr[mt * 2 + 1] + fmaf(-2.0f, acc[mt][nt][3], cn1);
                if (d00 < best[mt * 2])     { best[mt * 2] = d00;     bidx[mt * 2] = k0; }
                if (d01 < best[mt * 2])     { best[mt * 2] = d01;     bidx[mt * 2] = k0 + 1; }
                if (d10 < best[mt * 2 + 1]) { best[mt * 2 + 1] = d10; bidx[mt * 2 + 1] = k0; }
                if (d11 < best[mt * 2 + 1]) { best[mt * 2 + 1] = d11; bidx[mt * 2 + 1] = k0 + 1; }
            }
        }
        __syncthreads();
        if (ch + 2 < 8) { copyC(ch + 2, buf); CP_COMMIT(); }
        if (ch + 1 < 8) {
            if (ch + 2 < 8) CP_WAIT1(); else CP_WAIT0();
            __syncthreads();
        }
        buf ^= 1;
    }

    float* redV = CbB[0];
    int*   redI = (int*)(CbB[0] + 1024);
    #pragma unroll
    for (int s = 0; s < 4; s++) {
        int row = wy * 32 + (s >> 1) * 16 + (s & 1) * 8 + grp;
        redV[row * 8 + wx * 4 + ctg] = best[s];
        redI[row * 8 + wx * 4 + ctg] = bidx[s];
    }
    __syncthreads();

    if (tid < 128) {
        int   r  = tid;
        float bv = redV[r * 8];
        int   bi = redI[r * 8];
        #pragma unroll
        for (int t = 1; t < 8; t++) {
            float v  = redV[r * 8 + t];
            int   i2 = redI[r * 8 + t];
            if (v < bv || (v == bv && i2 < bi)) { bv = v; bi = i2; }
        }
        int grow = row0 + r;
        idxf[(size_t)grow * GRP + g] = (float)bi;

        const float* cw  = cgb + (size_t)bi * GD;
        float*       zqo = zq + (size_t)grow * LATENT + g * GD;
        float diff2 = 0.0f;
        #pragma unroll
        for (int dq = 0; dq < 8; dq++) {
            float4 c4 = *(const float4*)&cw[dq * 4];
            float d0 = c4.x - Zs[r * 36 + dq * 4 + 0];
            float d1 = c4.y - Zs[r * 36 + dq * 4 + 1];
            float d2 = c4.z - Zs[r * 36 + dq * 4 + 2];
            float d3 = c4.w - Zs[r * 36 + dq * 4 + 3];
            diff2 = fmaf(d0, d0, diff2);
            diff2 = fmaf(d1, d1, diff2);
            diff2 = fmaf(d2, d2, diff2);
            diff2 = fmaf(d3, d3, diff2);
            *(float4*)&zqo[dq * 4] = c4;
        }
        lsum[r] = diff2;
    }
    __syncthreads();

    __shared__ bool is_last;
    if (tid == 0) {
        float s = 0.0f;
        for (int r = 0; r < 128; r++) s += lsum[r];
        losspart[blockIdx.y * gridDim.x + blockIdx.x] = s;
        __threadfence();
        unsigned int t = atomicAdd(&g_cnt, 1u);
        is_last = (t == (unsigned int)(gridDim.x * gridDim.y - 1));
    }
    __syncthreads();

    if (is_last) {
        int npart = gridDim.x * gridDim.y;
        float v = 0.0f;
        for (int i = tid; i < npart; i += 256) v += losspart[i];
        redV[tid] = v;
        __syncthreads();
        for (int off = 128; off > 0; off >>= 1) {
            if (tid < off) redV[tid] += redV[tid + off];
            __syncthreads();
        }
        if (tid == 0) {
            lossout[0] = redV[0] * (1.0f / 1024000.0f);
            g_cnt = 0;
        }
    }
}

// ===========================================================================
extern "C" void kernel_launch(void* const* d_in, const int* in_sizes, int n_in,
                              void* d_out, int out_size)
{
    const float* bands = (const float*)d_in[0];
    const float* ew1   = (const float*)d_in[1];
    const float* eb1   = (const float*)d_in[2];
    const float* ew2   = (const float*)d_in[3];
    const float* eb2   = (const float*)d_in[4];
    const float* cb    = (const float*)d_in[5];
    const float* dw1   = (const float*)d_in[6];
    const float* db1   = (const float*)d_in[7];
    const float* dw2   = (const float*)d_in[8];
    const float* db2   = (const float*)d_in[9];

    float* out  = (float*)d_out;
    float* bhat = out;
    float* ze   = bhat + 1024000;
    float* zq   = ze   + 4096000;
    float* idxf = zq   + 4096000;
    float* loss = idxf + 128000;

    float *hid, *lpart, *wtb, *wtr, *cbb, *cbr, *cn2;
    cudaGetSymbolAddress((void**)&hid,   g_hidden);
    cudaGetSymbolAddress((void**)&lpart, g_loss_part);
    cudaGetSymbolAddress((void**)&wtb,   g_wtb);
    cudaGetSymbolAddress((void**)&wtr,   g_wtr);
    cudaGetSymbolAddress((void**)&cbb,   g_cbb);
    cudaGetSymbolAddress((void**)&cbr,   g_cbr);
    cudaGetSymbolAddress((void**)&cn2,   g_cn2);

    float* e1b = wtb;          float* e1r = wtr;
    float* e2b = wtb + 32768;  float* e2r = wtr + 32768;
    float* d1b = wtb + 163840; float* d1r = wtr + 163840;
    float* d2b = wtb + 294912; float* d2r = wtr + 294912;

    const int SM128 = (2 * 128 * 36 + 4 * 32 * 136) * 4;   // 106496
    const int SM64  = (2 * 64 * 36 + 4 * 32 * 72) * 4;     // 55296
    cudaFuncSetAttribute((const void*)tgemm<128, 128, true >,
                         cudaFuncAttributeMaxDynamicSharedMemorySize, SM128);
    cudaFuncSetAttribute((const void*)tgemm<128, 128, false>,
                         cudaFuncAttributeMaxDynamicSharedMemorySize, SM128);
    cudaFuncSetAttribute((const void*)tgemm<64, 64, false>,
                         cudaFuncAttributeMaxDynamicSharedMemorySize, SM64);
    cudaFuncSetAttribute((const void*)vq_kernel,
                         cudaFuncAttributeMaxDynamicSharedMemorySize, VQ_SMEM_FLOATS * 4);

    // Fused splits (2 launches)
    split_all<<<(WT_TOTAL + 255) / 256, 256>>>(ew1, ew2, dw1, dw2, wtb, wtr);
    csplit<<<(GRP * KCB + 255) / 256, 256>>>(cb, cbb, cbr, cn2);

    // Encoder
    tgemm<128, 128, true ><<<dim3(HIDDEN / 128, NROWS / 128), 256, SM128>>>(
        bands, e1b, e1r, eb1, hid, NROWS, HIDDEN, NBANDS);
    tgemm<128, 128, false><<<dim3(LATENT / 128, NROWS / 128), 256, SM128>>>(
        hid, e2b, e2r, eb2, ze, NROWS, LATENT, HIDDEN);

    // Vector quantization (tensor-core cross term + fused loss)
    vq_kernel<<<dim3(NROWS / 128, GRP), 256, VQ_SMEM_FLOATS * 4>>>(
        ze, cb, cbb, cbr, cn2, zq, idxf, lpart, loss);

    // Decoder
    tgemm<128, 128, true ><<<dim3(HIDDEN / 128, NROWS / 128), 256, SM128>>>(
        zq, d1b, d1r, db1, hid, NROWS, HIDDEN, LATENT);
    tgemm<64, 64, false><<<dim3(NBANDS / 64, NROWS / 64), 256, SM64>>>(
        hid, d2b, d2r, db2, bhat, NROWS, NBANDS, HIDDEN);
}

// round 9
// speedup vs baseline: 1.3894x; 1.1472x over previous
#include <cuda_runtime.h>
#include <cstdint>
#include <cfloat>

#define NROWS   16000
#define NBANDS  64
#define HIDDEN  512
#define LATENT  256
#define GRP     8
#define GD      32
#define KCB     1024

__device__ float g_hidden[NROWS * HIDDEN];
__device__ float g_loss_part[1024];
__device__ unsigned int g_cnt = 0;

// Packed fragment-quad weights: per matrix [K][N] -> float4[kg][n][ctg] where
// quad = (big[kg*8+ctg][n], big[kg*8+4+ctg][n], res[kg*8+ctg][n], res[kg*8+4+ctg][n])
// float4 counts: e1 16384 | e2 65536 | d1 65536 | d2 16384  (total 163840)
__device__ float4 g_wtp[163840];
// Packed codebook: [g][kg(4)][cw(1024)][ctg(4)] float4  (16384 per group)
__device__ float4 g_cbp[GRP * 16384];
__device__ float  g_cn2[GRP * KCB];

// ===========================================================================
// Helpers
// ===========================================================================
__device__ __forceinline__ uint32_t smem_u32(const void* p) {
    uint32_t a;
    asm("{ .reg .u64 t; cvta.to.shared.u64 t, %1; cvt.u32.u64 %0, t; }" : "=r"(a) : "l"(p));
    return a;
}
__device__ __forceinline__ uint32_t tf32_of(float x) {
    uint32_t r;
    asm("cvt.rna.tf32.f32 %0, %1;" : "=r"(r) : "f"(x));
    return r;
}
__device__ __forceinline__ void cp_async16(uint32_t saddr, const void* g) {
    asm volatile("cp.async.cg.shared.global [%0], [%1], 16;" :: "r"(saddr), "l"(g));
}
#define CP_COMMIT() asm volatile("cp.async.commit_group;" ::: "memory")
#define CP_WAIT0()  asm volatile("cp.async.wait_group 0;" ::: "memory")
#define CP_WAIT1()  asm volatile("cp.async.wait_group 1;" ::: "memory")

__device__ __forceinline__ void mma_tf32(float* c, const uint32_t* a, uint32_t b0, uint32_t b1) {
    asm volatile(
        "mma.sync.aligned.m16n8k8.row.col.f32.tf32.tf32.f32 "
        "{%0,%1,%2,%3}, {%4,%5,%6,%7}, {%8,%9}, {%0,%1,%2,%3};"
        : "+f"(c[0]), "+f"(c[1]), "+f"(c[2]), "+f"(c[3])
        : "r"(a[0]), "r"(a[1]), "r"(a[2]), "r"(a[3]), "r"(b0), "r"(b1));
}

// ===========================================================================
// Split kernels -> packed fragment-quad format
// ===========================================================================
__global__ void split_all(const float* __restrict__ ew1, const float* __restrict__ ew2,
                          const float* __restrict__ dw1, const float* __restrict__ dw2,
                          float4* __restrict__ wtp)
{
    int i = blockIdx.x * 256 + threadIdx.x;    // float4 index
    const float* w; int N, off;
    if      (i < 16384)  { w = ew1; N = 512; off = i; }
    else if (i < 81920)  { w = ew2; N = 256; off = i - 16384; }
    else if (i < 147456) { w = dw1; N = 512; off = i - 81920; }
    else if (i < 163840) { w = dw2; N = 64;  off = i - 147456; }
    else return;
    int ctg = off & 3;
    int rem = off >> 2;
    int n = rem % N, kg = rem / N;
    float x0 = w[(size_t)(kg * 8 + ctg) * N + n];
    float x1 = w[(size_t)(kg * 8 + 4 + ctg) * N + n];
    float b0 = __uint_as_float(tf32_of(x0));
    float b1 = __uint_as_float(tf32_of(x1));
    float r0 = __uint_as_float(tf32_of(x0 - b0));
    float r1 = __uint_as_float(tf32_of(x1 - b1));
    wtp[i] = make_float4(b0, b1, r0, r1);
}

__global__ void csplit(const float* __restrict__ cb, float4* __restrict__ cbp,
                       float* __restrict__ cn2)
{
    int row = blockIdx.x * 256 + threadIdx.x;      // 0..8191 (g*1024+cw)
    if (row >= GRP * KCB) return;
    int g = row >> 10, cw = row & 1023;
    const float* src = cb + (size_t)row * GD;
    float bg[GD], rs[GD], s = 0.0f;
    #pragma unroll
    for (int d = 0; d < GD; d++) {
        float x = src[d];
        bg[d] = __uint_as_float(tf32_of(x));
        rs[d] = __uint_as_float(tf32_of(x - bg[d]));
        s = fmaf(x, x, s);
    }
    cn2[row] = s;
    float4* dst = cbp + (size_t)g * 16384;
    #pragma unroll
    for (int kg = 0; kg < 4; kg++)
        #pragma unroll
        for (int ctg = 0; ctg < 4; ctg++)
            dst[(kg * 1024 + cw) * 4 + ctg] =
                make_float4(bg[kg * 8 + ctg], bg[kg * 8 + 4 + ctg],
                            rs[kg * 8 + ctg], rs[kg * 8 + 4 + ctg]);
}

// ===========================================================================
// Tensor GEMM (3xtf32), packed-quad B: C = act(A[M,K] @ W[K,N] + bias)
// BM in {64,128}, BK=32 (4 kgroups), 8 warps (4M x 2N).
// B fragment = single LDS.128. A converted in-loop.
// ===========================================================================
template<int BM, int BN, bool RELU>
__global__ __launch_bounds__(256, 2) void tgemm(
    const float* __restrict__ A,
    const float4* __restrict__ Wp,        // packed [kg][N][ctg]
    const float* __restrict__ bias, float* __restrict__ C,
    int M, int N, int K)
{
    constexpr int BK = 32;
    constexpr int ASTR = 36;
    constexpr int WN = BN / 2, NT = WN / 8;
    constexpr int MT = BM / 64;
    constexpr int ASZ = BM * ASTR;                 // floats
    constexpr int BSZ4 = 4 * BN * 4;               // float4 per buffer
    constexpr int A_Q = BM / 32;
    constexpr int B_Q = BN / 16;                   // f4 copies per thread

    extern __shared__ __align__(16) float sm[];
    float*  AsBuf[2] = { sm, sm + ASZ };
    float4* BpBuf[2] = { (float4*)(sm + 2 * ASZ), (float4*)(sm + 2 * ASZ) + BSZ4 };

    const int tid = threadIdx.x;
    const int wid = tid >> 5;
    const int lane = tid & 31;
    const int grp = lane >> 2;
    const int ctg = lane & 3;
    const int wy  = wid & 3;
    const int wx  = wid >> 2;
    const int m0  = blockIdx.y * BM;
    const int n0  = blockIdx.x * BN;

    float acc[MT][NT][4];
    #pragma unroll
    for (int mt = 0; mt < MT; mt++)
        #pragma unroll
        for (int nt = 0; nt < NT; nt++)
            #pragma unroll
            for (int q = 0; q < 4; q++) acc[mt][nt][q] = 0.0f;

    auto copy_chunk = [&](int ch, int buf) {
        const int k0 = ch * BK;
        const int kg0 = ch * 4;
        uint32_t as = smem_u32(AsBuf[buf]);
        uint32_t bs = smem_u32(BpBuf[buf]);
        #pragma unroll
        for (int u = 0; u < A_Q; u++) {
            int f = tid + u * 256;
            int r = f >> 3, q = f & 7;
            cp_async16(as + (uint32_t)(r * ASTR + q * 4) * 4,
                       &A[(size_t)(m0 + r) * K + k0 + q * 4]);
        }
        #pragma unroll
        for (int u = 0; u < B_Q; u++) {
            int f = tid + u * 256;
            int kgl = f / (BN * 4);
            int rem = f % (BN * 4);
            int nl = rem >> 2, c = rem & 3;
            cp_async16(bs + (uint32_t)f * 16,
                       &Wp[((size_t)(kg0 + kgl) * N + n0 + nl) * 4 + c]);
        }
        CP_COMMIT();
    };

    auto compute = [&](int buf) {
        const float*  As = AsBuf[buf];
        const float4* Bp = BpBuf[buf];
        #pragma unroll
        for (int ks = 0; ks < 4; ks++) {
            const int k8 = ks * 8;
            uint32_t abig[MT][4], ares[MT][4];
            #pragma unroll
            for (int mt = 0; mt < MT; mt++) {
                const int rb = wy * (BM / 4) + mt * 16;
                float af[4];
                af[0] = As[(rb + grp) * ASTR + k8 + ctg];
                af[1] = As[(rb + 8 + grp) * ASTR + k8 + ctg];
                af[2] = As[(rb + grp) * ASTR + k8 + 4 + ctg];
                af[3] = As[(rb + 8 + grp) * ASTR + k8 + 4 + ctg];
                #pragma unroll
                for (int q = 0; q < 4; q++) {
                    abig[mt][q] = tf32_of(af[q]);
                    ares[mt][q] = tf32_of(af[q] - __uint_as_float(abig[mt][q]));
                }
            }
            #pragma unroll
            for (int nt = 0; nt < NT; nt++) {
                const int col = wx * WN + nt * 8 + grp;
                float4 qd = Bp[(ks * BN + col) * 4 + ctg];
                uint32_t bb0 = __float_as_uint(qd.x);
                uint32_t bb1 = __float_as_uint(qd.y);
                uint32_t br0 = __float_as_uint(qd.z);
                uint32_t br1 = __float_as_uint(qd.w);
                #pragma unroll
                for (int mt = 0; mt < MT; mt++) {
                    mma_tf32(acc[mt][nt], abig[mt], bb0, bb1);
                    mma_tf32(acc[mt][nt], abig[mt], br0, br1);
                    mma_tf32(acc[mt][nt], ares[mt], bb0, bb1);
                }
            }
        }
    };

    const int nch = K / BK;
    copy_chunk(0, 0);
    for (int ch = 0; ch < nch; ch++) {
        const int cur = ch & 1;
        if (ch + 1 < nch) { copy_chunk(ch + 1, cur ^ 1); CP_WAIT1(); }
        else              { CP_WAIT0(); }
        __syncthreads();
        compute(cur);
        __syncthreads();
    }

    #pragma unroll
    for (int mt = 0; mt < MT; mt++) {
        const int r0 = m0 + wy * (BM / 4) + mt * 16 + grp;
        #pragma unroll
        for (int nt = 0; nt < NT; nt++) {
            const int col = n0 + wx * WN + nt * 8 + 2 * ctg;
            float b0 = bias[col], b1 = bias[col + 1];
            float2 v0, v1;
            v0.x = acc[mt][nt][0] + b0; v0.y = acc[mt][nt][1] + b1;
            v1.x = acc[mt][nt][2] + b0; v1.y = acc[mt][nt][3] + b1;
            if (RELU) {
                v0.x = fmaxf(v0.x, 0.0f); v0.y = fmaxf(v0.y, 0.0f);
                v1.x = fmaxf(v1.x, 0.0f); v1.y = fmaxf(v1.y, 0.0f);
            }
            *(float2*)&C[(size_t)r0 * N + col] = v0;
            *(float2*)&C[(size_t)(r0 + 8) * N + col] = v1;
        }
    }
}

// ===========================================================================
// VQ kernel: packed-quad codebook (1 LDS.128 per fragment), tensor 3xtf32,
// in-loop Z conversion, fused deterministic loss.
// Smem floats: Zs 4608 | CbP 2*8192 | CNs 256 | zn 128 | lsum 128 = 21504
// ===========================================================================
#define VQ_SMEM_FLOATS 21504

__global__ __launch_bounds__(256, 2) void vq_kernel(
    const float* __restrict__ ze,
    const float* __restrict__ cb,
    const float4* __restrict__ cbp,
    const float* __restrict__ cn2,
    float* __restrict__ zq,
    float* __restrict__ idxf,
    float* __restrict__ losspart,
    float* __restrict__ lossout)
{
    extern __shared__ __align__(16) float sm[];
    float*  Zs = sm;                                       // [128][36]
    float4* CbP[2] = { (float4*)(sm + 4608), (float4*)(sm + 4608) + 2048 };
    float* CNs  = sm + 4608 + 16384;                       // [2][128]
    float* zn   = CNs + 256;
    float* lsum = zn + 128;

    const int tid = threadIdx.x;
    const int wid = tid >> 5;
    const int lane = tid & 31;
    const int grp = lane >> 2;
    const int ctg = lane & 3;
    const int wy  = wid & 3;
    const int wx  = wid >> 2;
    const int g    = blockIdx.y;
    const int row0 = blockIdx.x * 128;

    const float*  zbase = ze  + (size_t)row0 * LATENT + g * GD;
    const float*  cgb   = cb  + (size_t)g * KCB * GD;
    const float4* cbpg  = cbp + (size_t)g * 16384;
    const float*  cng   = cn2 + g * KCB;

    auto copyC = [&](int ch, int buf) {
        uint32_t bs = smem_u32(CbP[buf]);
        #pragma unroll
        for (int u = 0; u < 8; u++) {            // 2048 f4 units
            int f = tid + u * 256;
            int kgl = f >> 9;                    // /512
            int rem = f & 511;
            int cwl = rem >> 2, c = rem & 3;
            cp_async16(bs + (uint32_t)f * 16,
                       &cbpg[((size_t)kgl * 1024 + ch * 128 + cwl) * 4 + c]);
        }
        if (tid < 32)
            cp_async16(smem_u32(CNs + buf * 128) + tid * 16, cng + ch * 128 + tid * 4);
    };

    {
        uint32_t zs = smem_u32(Zs);
        #pragma unroll
        for (int u = 0; u < 4; u++) {
            int f = tid + u * 256;
            int r = f >> 3, q = f & 7;
            cp_async16(zs + (uint32_t)(r * 36 + q * 4) * 4,
                       zbase + (size_t)r * LATENT + q * 4);
        }
        copyC(0, 0);
        CP_COMMIT();
        copyC(1, 1);
        CP_COMMIT();
    }
    CP_WAIT1();
    __syncthreads();

    if (tid < 128) {
        float s = 0.0f;
        #pragma unroll
        for (int d = 0; d < 32; d++) { float z = Zs[tid * 36 + d]; s = fmaf(z, z, s); }
        zn[tid] = s;
    }
    __syncthreads();

    float znr[4];
    znr[0] = zn[wy * 32 + grp];
    znr[1] = zn[wy * 32 + 8 + grp];
    znr[2] = zn[wy * 32 + 16 + grp];
    znr[3] = zn[wy * 32 + 24 + grp];

    float best[4];
    int   bidx[4];
    #pragma unroll
    for (int i = 0; i < 4; i++) { best[i] = FLT_MAX; bidx[i] = 0; }

    int buf = 0;
    for (int ch = 0; ch < 8; ch++) {
        float acc[2][8][4];
        #pragma unroll
        for (int mt = 0; mt < 2; mt++)
            #pragma unroll
            for (int nt = 0; nt < 8; nt++)
                #pragma unroll
                for (int q = 0; q < 4; q++) acc[mt][nt][q] = 0.0f;

        const float4* Bp = CbP[buf];
        #pragma unroll
        for (int ks = 0; ks < 4; ks++) {
            const int k8 = ks * 8;
            uint32_t abig[2][4], ares[2][4];
            #pragma unroll
            for (int mt = 0; mt < 2; mt++) {
                const int rb = wy * 32 + mt * 16;
                float af[4];
                af[0] = Zs[(rb + grp) * 36 + k8 + ctg];
                af[1] = Zs[(rb + 8 + grp) * 36 + k8 + ctg];
                af[2] = Zs[(rb + grp) * 36 + k8 + 4 + ctg];
                af[3] = Zs[(rb + 8 + grp) * 36 + k8 + 4 + ctg];
                #pragma unroll
                for (int q = 0; q < 4; q++) {
                    abig[mt][q] = tf32_of(af[q]);
                    ares[mt][q] = tf32_of(af[q] - __uint_as_float(abig[mt][q]));
                }
            }
            #pragma unroll
            for (int nt = 0; nt < 8; nt++) {
                const int col = wx * 64 + nt * 8 + grp;
                float4 qd = Bp[(ks * 128 + col) * 4 + ctg];
                uint32_t cb0 = __float_as_uint(qd.x);
                uint32_t cb1 = __float_as_uint(qd.y);
                uint32_t cr0 = __float_as_uint(qd.z);
                uint32_t cr1 = __float_as_uint(qd.w);
                #pragma unroll
                for (int mt = 0; mt < 2; mt++) {
                    mma_tf32(acc[mt][nt], abig[mt], cb0, cb1);
                    mma_tf32(acc[mt][nt], abig[mt], cr0, cr1);
                    mma_tf32(acc[mt][nt], ares[mt], cb0, cb1);
                }
            }
        }

        const float* CNc = CNs + buf * 128;
        #pragma unroll
        for (int nt = 0; nt < 8; nt++) {
            const int cbase = wx * 64 + nt * 8 + 2 * ctg;
            float cn0 = CNc[cbase], cn1 = CNc[cbase + 1];
            int   k0  = ch * 128 + cbase;
            #pragma unroll
            for (int mt = 0; mt < 2; mt++) {
                float d00 = znr[mt * 2 + 0] + fmaf(-2.0f, acc[mt][nt][0], cn0);
                float d01 = znr[mt * 2 + 0] + fmaf(-2.0f, acc[mt][nt][1], cn1);
                float d10 = znr[mt * 2 + 1] + fmaf(-2.0f, acc[mt][nt][2], cn0);
                float d11 = znr[mt * 2 + 1] + fmaf(-2.0f, acc[mt][nt][3], cn1);
                if (d00 < best[mt * 2])     { best[mt * 2] = d00;     bidx[mt * 2] = k0; }
                if (d01 < best[mt * 2])     { best[mt * 2] = d01;     bidx[mt * 2] = k0 + 1; }
                if (d10 < best[mt * 2 + 1]) { best[mt * 2 + 1] = d10; bidx[mt * 2 + 1] = k0; }
                if (d11 < best[mt * 2 + 1]) { best[mt * 2 + 1] = d11; bidx[mt * 2 + 1] = k0 + 1; }
            }
        }
        __syncthreads();
        if (ch + 2 < 8) { copyC(ch + 2, buf); CP_COMMIT(); }
        if (ch + 1 < 8) {
            if (ch + 2 < 8) CP_WAIT1(); else CP_WAIT0();
            __syncthreads();
        }
        buf ^= 1;
    }

    // Cross-thread argmin reduction (8 slots/row), scratch over CbP area
    float* redV = (float*)CbP[0];
    int*   redI = (int*)((float*)CbP[0] + 1024);
    #pragma unroll
    for (int s = 0; s < 4; s++) {
        int row = wy * 32 + (s >> 1) * 16 + (s & 1) * 8 + grp;
        redV[row * 8 + wx * 4 + ctg] = best[s];
        redI[row * 8 + wx * 4 + ctg] = bidx[s];
    }
    __syncthreads();

    if (tid < 128) {
        int   r  = tid;
        float bv = redV[r * 8];
        int   bi = redI[r * 8];
        #pragma unroll
        for (int t = 1; t < 8; t++) {
            float v  = redV[r * 8 + t];
            int   i2 = redI[r * 8 + t];
            if (v < bv || (v == bv && i2 < bi)) { bv = v; bi = i2; }
        }
        int grow = row0 + r;
        idxf[(size_t)grow * GRP + g] = (float)bi;

        const float* cw  = cgb + (size_t)bi * GD;
        float*       zqo = zq + (size_t)grow * LATENT + g * GD;
        float diff2 = 0.0f;
        #pragma unroll
        for (int dq = 0; dq < 8; dq++) {
            float4 c4 = *(const float4*)&cw[dq * 4];
            float d0 = c4.x - Zs[r * 36 + dq * 4 + 0];
            float d1 = c4.y - Zs[r * 36 + dq * 4 + 1];
            float d2 = c4.z - Zs[r * 36 + dq * 4 + 2];
            float d3 = c4.w - Zs[r * 36 + dq * 4 + 3];
            diff2 = fmaf(d0, d0, diff2);
            diff2 = fmaf(d1, d1, diff2);
            diff2 = fmaf(d2, d2, diff2);
            diff2 = fmaf(d3, d3, diff2);
            *(float4*)&zqo[dq * 4] = c4;
        }
        lsum[r] = diff2;
    }
    __syncthreads();

    __shared__ bool is_last;
    if (tid == 0) {
        float s = 0.0f;
        for (int r = 0; r < 128; r++) s += lsum[r];
        losspart[blockIdx.y * gridDim.x + blockIdx.x] = s;
        __threadfence();
        unsigned int t = atomicAdd(&g_cnt, 1u);
        is_last = (t == (unsigned int)(gridDim.x * gridDim.y - 1));
    }
    __syncthreads();

    if (is_last) {
        int npart = gridDim.x * gridDim.y;
        float v = 0.0f;
        for (int i = tid; i < npart; i += 256) v += losspart[i];
        redV[tid] = v;
        __syncthreads();
        for (int off = 128; off > 0; off >>= 1) {
            if (tid < off) redV[tid] += redV[tid + off];
            __syncthreads();
        }
        if (tid == 0) {
            lossout[0] = redV[0] * (1.0f / 1024000.0f);
            g_cnt = 0;
        }
    }
}

// ===========================================================================
extern "C" void kernel_launch(void* const* d_in, const int* in_sizes, int n_in,
                              void* d_out, int out_size)
{
    const float* bands = (const float*)d_in[0];
    const float* ew1   = (const float*)d_in[1];
    const float* eb1   = (const float*)d_in[2];
    const float* ew2   = (const float*)d_in[3];
    const float* eb2   = (const float*)d_in[4];
    const float* cb    = (const float*)d_in[5];
    const float* dw1   = (const float*)d_in[6];
    const float* db1   = (const float*)d_in[7];
    const float* dw2   = (const float*)d_in[8];
    const float* db2   = (const float*)d_in[9];

    float* out  = (float*)d_out;
    float* bhat = out;
    float* ze   = bhat + 1024000;
    float* zq   = ze   + 4096000;
    float* idxf = zq   + 4096000;
    float* loss = idxf + 128000;

    float *hid, *lpart, *cn2;
    float4 *wtp, *cbp;
    cudaGetSymbolAddress((void**)&hid,   g_hidden);
    cudaGetSymbolAddress((void**)&lpart, g_loss_part);
    cudaGetSymbolAddress((void**)&wtp,   g_wtp);
    cudaGetSymbolAddress((void**)&cbp,   g_cbp);
    cudaGetSymbolAddress((void**)&cn2,   g_cn2);

    const float4* e1p = wtp;
    const float4* e2p = wtp + 16384;
    const float4* d1p = wtp + 81920;
    const float4* d2p = wtp + 147456;

    const int SM128 = (2 * 128 * 36 + 2 * 4 * 128 * 16) * 4;   // 102400
    const int SM64  = (2 * 64 * 36 + 2 * 4 * 64 * 16) * 4;     // 51200
    cudaFuncSetAttribute((const void*)tgemm<128, 128, true >,
                         cudaFuncAttributeMaxDynamicSharedMemorySize, SM128);
    cudaFuncSetAttribute((const void*)tgemm<128, 128, false>,
                         cudaFuncAttributeMaxDynamicSharedMemorySize, SM128);
    cudaFuncSetAttribute((const void*)tgemm<64, 64, false>,
                         cudaFuncAttributeMaxDynamicSharedMemorySize, SM64);
    cudaFuncSetAttribute((const void*)vq_kernel,
                         cudaFuncAttributeMaxDynamicSharedMemorySize, VQ_SMEM_FLOATS * 4);

    // Packed splits (2 launches)
    split_all<<<640, 256>>>(ew1, ew2, dw1, dw2, wtp);
    csplit<<<32, 256>>>(cb, cbp, cn2);

    // Encoder
    tgemm<128, 128, true ><<<dim3(HIDDEN / 128, NROWS / 128), 256, SM128>>>(
        bands, e1p, eb1, hid, NROWS, HIDDEN, NBANDS);
    tgemm<128, 128, false><<<dim3(LATENT / 128, NROWS / 128), 256, SM128>>>(
        hid, e2p, eb2, ze, NROWS, LATENT, HIDDEN);

    // Vector quantization (tensor-core cross term + fused loss)
    vq_kernel<<<dim3(NROWS / 128, GRP), 256, VQ_SMEM_FLOATS * 4>>>(
        ze, cb, cbp, cn2, zq, idxf, lpart, loss);

    // Decoder
    tgemm<128, 128, true ><<<dim3(HIDDEN / 128, NROWS / 128), 256, SM128>>>(
        zq, d1p, db1, hid, NROWS, HIDDEN, LATENT);
    tgemm<64, 64, false><<<dim3(NBANDS / 64, NROWS / 64), 256, SM64>>>(
        hid, d2p, db2, bhat, NROWS, NBANDS, HIDDEN);
}